// round 14
// baseline (speedup 1.0000x reference)
#include <cuda_runtime.h>
#include <cuda_fp16.h>
#include <cstdint>

#define M_B    8192
#define LDACT  3584          // halfs per act row: [x | u | wB | wA]
#define COL_WB 1536
#define COL_WA 2560
#define N_LOOP 3             // odd: w0->wA, ends in wB

#define BM 128
#define BN 128
#define BK 32
#define LDSH 40
#define A_HALFS (BM * LDSH)
#define STAGE_HALFS (2 * A_HALFS)
#define STAGE_BYTES (STAGE_HALFS * 2)
#define STAGES 5
#define PREFETCH 4
#define SMEM_BYTES (STAGES * STAGE_BYTES)   // 102400

__device__ __half g_act [(size_t)M_B * LDACT];
__device__ float  g_b   [(size_t)M_B * 1024];
__device__ float  g_P   [(size_t)M_B * 1536];   // [x|u] @ WXY[:, :1536]
__device__ __half g_WbT [1024 * 1536];
__device__ __half g_WXY [1536 * 2560];
__device__ __half g_D11T[1024 * 1024];

__device__ __forceinline__ uint32_t s2u(const void* p) {
    uint32_t a;
    asm("{ .reg .u64 t; cvta.to.shared.u64 t, %1; cvt.u32.u64 %0, t; }" : "=r"(a) : "l"(p));
    return a;
}
__device__ __forceinline__ void cpa16(uint32_t dst, const void* src) {
    asm volatile("cp.async.cg.shared.global [%0], [%1], 16;" :: "r"(dst), "l"(src) : "memory");
}
__device__ __forceinline__ float fast_tanh(float x) {
    float t = __expf(2.0f * x);
    return 1.0f - __fdividef(2.0f, t + 1.0f);
}
__device__ __forceinline__ void ldm4(uint32_t* r, uint32_t addr) {
    asm volatile("ldmatrix.sync.aligned.m8n8.x4.shared.b16 {%0,%1,%2,%3}, [%4];"
                 : "=r"(r[0]), "=r"(r[1]), "=r"(r[2]), "=r"(r[3]) : "r"(addr));
}
__device__ __forceinline__ void mma_f16(float* d, const uint32_t* a, uint32_t b0, uint32_t b1) {
    asm volatile(
        "mma.sync.aligned.m16n8k16.row.col.f32.f16.f16.f32 "
        "{%0,%1,%2,%3},{%4,%5,%6,%7},{%8,%9},{%0,%1,%2,%3};"
        : "+f"(d[0]), "+f"(d[1]), "+f"(d[2]), "+f"(d[3])
        : "r"(a[0]), "r"(a[1]), "r"(a[2]), "r"(a[3]), "r"(b0), "r"(b1));
}

enum { EPI_ST = 0, EPI_TANH = 1, EPI_B = 2, EPI_XYP = 3, EPI_ACC = 4 };

template <int EPI>
__global__ __launch_bounds__(128, 2)
void ren_gemm(const __half* __restrict__ Ap, int lda,
              const __half* __restrict__ Bp, int ldb, int nchunk,
              void* __restrict__ OutV, int ldo,
              const float* __restrict__ Badd, int ldadd,
              void* __restrict__ Out2V)
{
    extern __shared__ __half sm[];
    const uint32_t smu = s2u(sm);
    const int tid  = threadIdx.x;
    const int lane = tid & 31, wid = tid >> 5;
    const int m0 = blockIdx.y * BM, n0 = blockIdx.x * BN;

    const __half* gA[4]; const __half* gB[4];
    uint32_t oA[4], oB[4];
    #pragma unroll
    for (int i = 0; i < 4; ++i) {
        int c = tid + i * 128;
        int r = c >> 2, ks = c & 3;
        gA[i] = Ap + (size_t)(m0 + r) * lda + ks * 8;
        gB[i] = Bp + (size_t)(n0 + r) * ldb + ks * 8;
        oA[i] = (uint32_t)(r * LDSH + ks * 8) * 2u;
        oB[i] = (uint32_t)(A_HALFS + r * LDSH + ks * 8) * 2u;
    }

    const int l4 = lane >> 2, lq = lane & 3;
    const int mw = (wid >> 1) * 64, nw = (wid & 1) * 64;

    const uint32_t aRow = (uint32_t)(mw + (lane & 7) + (lane & 8)) * LDSH + ((lane & 16) >> 1);
    const uint32_t bRow = (uint32_t)(nw + (lane & 7) + ((lane & 16) >> 1)) * LDSH + (lane & 8);

    float acc[4][8][4];
    #pragma unroll
    for (int i = 0; i < 4; ++i)
        #pragma unroll
        for (int j = 0; j < 8; ++j)
            #pragma unroll
            for (int q = 0; q < 4; ++q) acc[i][j][q] = 0.0f;

    #pragma unroll
    for (int s = 0; s < PREFETCH; ++s) {
        uint32_t sb = smu + s * STAGE_BYTES;
        #pragma unroll
        for (int i = 0; i < 4; ++i) { cpa16(sb + oA[i], gA[i]); gA[i] += BK; }
        #pragma unroll
        for (int i = 0; i < 4; ++i) { cpa16(sb + oB[i], gB[i]); gB[i] += BK; }
        asm volatile("cp.async.commit_group;" ::: "memory");
    }

    int stage = 0;
    for (int c = 0; c < nchunk; ++c) {
        asm volatile("cp.async.wait_group %0;" :: "n"(PREFETCH - 1) : "memory");
        __syncthreads();

        const uint32_t sA = smu + stage * STAGE_BYTES;
        const uint32_t sB = sA + A_HALFS * 2;
        #pragma unroll
        for (int kk = 0; kk < 2; ++kk) {
            uint32_t a[4][4], bf[4][4];
            #pragma unroll
            for (int mt = 0; mt < 4; ++mt)
                ldm4(a[mt], sA + (aRow + mt * 16 * LDSH + kk * 16) * 2);
            #pragma unroll
            for (int nb = 0; nb < 4; ++nb)
                ldm4(bf[nb], sB + (bRow + nb * 16 * LDSH + kk * 16) * 2);
            #pragma unroll
            for (int mt = 0; mt < 4; ++mt)
                #pragma unroll
                for (int nt = 0; nt < 8; ++nt)
                    mma_f16(acc[mt][nt], a[mt],
                            bf[nt >> 1][(nt & 1) * 2], bf[nt >> 1][(nt & 1) * 2 + 1]);
        }

        if (c + PREFETCH < nchunk) {
            int s2 = stage + PREFETCH; if (s2 >= STAGES) s2 -= STAGES;
            uint32_t sb = smu + s2 * STAGE_BYTES;
            #pragma unroll
            for (int i = 0; i < 4; ++i) { cpa16(sb + oA[i], gA[i]); gA[i] += BK; }
            #pragma unroll
            for (int i = 0; i < 4; ++i) { cpa16(sb + oB[i], gB[i]); gB[i] += BK; }
        }
        asm volatile("cp.async.commit_group;" ::: "memory");
        if (++stage == STAGES) stage = 0;
    }

    float* dstF = (float*)OutV; int ldd = ldo, c0 = 0;
    if (EPI == EPI_XYP && n0 >= 1024) { dstF = (float*)Out2V; ldd = 512; c0 = 1024; }

    #pragma unroll
    for (int mt = 0; mt < 4; ++mt) {
        #pragma unroll
        for (int half = 0; half < 2; ++half) {
            const int r = m0 + mw + mt * 16 + l4 + half * 8;
            #pragma unroll
            for (int nt = 0; nt < 8; ++nt) {
                const int col = n0 + nw + nt * 8 + lq * 2;
                float v0 = acc[mt][nt][half * 2 + 0];
                float v1 = acc[mt][nt][half * 2 + 1];
                if (EPI == EPI_TANH) {
                    float2 bv = *(const float2*)(Badd + (size_t)r * ldadd + col);
                    __half2 h = __floats2half2_rn(fast_tanh(v0 + bv.x), fast_tanh(v1 + bv.y));
                    *(__half2*)((__half*)OutV + (size_t)r * ldo + col) = h;
                } else if (EPI == EPI_B) {
                    *(float2*)((float*)OutV + (size_t)r * ldo + col) = make_float2(v0, v1);
                    __half2 h = __floats2half2_rn(fast_tanh(v0), fast_tanh(v1));
                    *(__half2*)((__half*)Out2V + (size_t)r * LDACT + col) = h;
                } else if (EPI == EPI_XYP || EPI == EPI_ACC) {
                    float2 pv = *(const float2*)(Badd + (size_t)r * ldadd + col);
                    *(float2*)(dstF + (size_t)r * ldd + (col - c0)) =
                        make_float2(v0 + pv.x, v1 + pv.y);
                } else {  // EPI_ST
                    *(float2*)(dstF + (size_t)r * ldd + col) = make_float2(v0, v1);
                }
            }
        }
    }
}

// ---- merged prep: 4 weight transposes + activation pack in ONE launch ----
__device__ __forceinline__ void tile_transpose(
    float (*t)[33],
    const float* S0, int K0, const float* S1, int K1, const float* S2, int K2,
    int N, __half* OutT, int ldt, int xb, int yb)
{
    const int k0 = yb * 32, n0 = xb * 32;
    const int tx = threadIdx.x & 31, ty = threadIdx.x >> 5;
    #pragma unroll
    for (int j = 0; j < 4; ++j) {
        int k = k0 + ty + j * 8;
        const float* S; int kk;
        if (k < K0)           { S = S0; kk = k; }
        else if (k < K0 + K1) { S = S1; kk = k - K0; }
        else                  { S = S2; kk = k - K0 - K1; }
        t[ty + j * 8][tx] = S[(size_t)kk * N + n0 + tx];
    }
    __syncthreads();
    #pragma unroll
    for (int j = 0; j < 4; ++j) {
        int n = n0 + ty + j * 8;
        OutT[(size_t)n * ldt + k0 + tx] = __float2half_rn(t[tx][ty + j * 8]);
    }
}

#define NB_WBT  1536
#define NB_WXY1 2560
#define NB_WXY2 1280
#define NB_D11  1024
#define NB_T    (NB_WBT + NB_WXY1 + NB_WXY2 + NB_D11)
#define NB_PACK 24576

__global__ __launch_bounds__(256)
void prep_all(const float* __restrict__ C1,  const float* __restrict__ D12,
              const float* __restrict__ A,   const float* __restrict__ B2,
              const float* __restrict__ B1,  const float* __restrict__ C2,
              const float* __restrict__ D22, const float* __restrict__ D21,
              const float* __restrict__ D11, const float* __restrict__ x,
              const float* __restrict__ u,
              __half* __restrict__ WbT, __half* __restrict__ WXY,
              __half* __restrict__ D11T, __half* __restrict__ act)
{
    __shared__ float t[32][33];
    int bid = blockIdx.x;
    if (bid < NB_T) {
        if (bid < NB_WBT) {
            tile_transpose(t, C1, 1024, D12, 512, nullptr, 0, 1024,
                           WbT, 1536, bid & 31, bid >> 5);
        } else if (bid < NB_WBT + NB_WXY1) {
            int q = bid - NB_WBT;
            tile_transpose(t, A, 1024, B2, 512, B1, 1024, 1024,
                           WXY, 2560, q & 31, q >> 5);
        } else if (bid < NB_WBT + NB_WXY1 + NB_WXY2) {
            int q = bid - NB_WBT - NB_WXY1;
            tile_transpose(t, C2, 1024, D22, 512, D21, 1024, 512,
                           WXY + (size_t)1024 * 2560, 2560, q & 15, q >> 4);
        } else {
            int q = bid - (NB_WBT + NB_WXY1 + NB_WXY2);
            tile_transpose(t, D11, 1024, nullptr, 0, nullptr, 0, 1024,
                           D11T, 1024, q & 31, q >> 5);
        }
    } else {
        int idx = (bid - NB_T) * 256 + threadIdx.x;
        int row = idx / 768, c2 = idx % 768;
        float2 v = (c2 < 512) ? ((const float2*)x)[(size_t)row * 512 + c2]
                              : ((const float2*)u)[(size_t)row * 256 + (c2 - 512)];
        ((__half2*)act)[(size_t)row * (LDACT / 2) + c2] = __floats2half2_rn(v.x, v.y);
    }
}

extern "C" void kernel_launch(void* const* d_in, const int* in_sizes, int n_in,
                              void* d_out, int out_size)
{
    (void)in_sizes; (void)n_in; (void)out_size;
    const float* x   = (const float*)d_in[0];
    const float* u   = (const float*)d_in[1];
    const float* A   = (const float*)d_in[2];
    const float* B1  = (const float*)d_in[3];
    const float* B2  = (const float*)d_in[4];
    const float* C1  = (const float*)d_in[5];
    const float* D11 = (const float*)d_in[6];
    const float* D12 = (const float*)d_in[7];
    const float* C2  = (const float*)d_in[8];
    const float* D21 = (const float*)d_in[9];
    const float* D22 = (const float*)d_in[10];
    float* out = (float*)d_out;

    __half *act, *WbT, *WXY, *D11T; float *b, *P;
    cudaGetSymbolAddress((void**)&act,  g_act);
    cudaGetSymbolAddress((void**)&b,    g_b);
    cudaGetSymbolAddress((void**)&P,    g_P);
    cudaGetSymbolAddress((void**)&WbT,  g_WbT);
    cudaGetSymbolAddress((void**)&WXY,  g_WXY);
    cudaGetSymbolAddress((void**)&D11T, g_D11T);

    cudaFuncSetAttribute((const void*)ren_gemm<EPI_ST>,   cudaFuncAttributeMaxDynamicSharedMemorySize, SMEM_BYTES);
    cudaFuncSetAttribute((const void*)ren_gemm<EPI_TANH>, cudaFuncAttributeMaxDynamicSharedMemorySize, SMEM_BYTES);
    cudaFuncSetAttribute((const void*)ren_gemm<EPI_B>,    cudaFuncAttributeMaxDynamicSharedMemorySize, SMEM_BYTES);
    cudaFuncSetAttribute((const void*)ren_gemm<EPI_XYP>,  cudaFuncAttributeMaxDynamicSharedMemorySize, SMEM_BYTES);
    cudaFuncSetAttribute((const void*)ren_gemm<EPI_ACC>,  cudaFuncAttributeMaxDynamicSharedMemorySize, SMEM_BYTES);

    // lowest-priority side stream for P; fresh host objects per call.
    int prLo = 0, prHi = 0;
    cudaDeviceGetStreamPriorityRange(&prLo, &prHi);
    cudaStream_t s2 = 0;
    bool forked = (cudaStreamCreateWithPriority(&s2, cudaStreamNonBlocking, prLo) == cudaSuccess);
    cudaEvent_t ev0 = 0, ev2 = 0;
    if (forked) {
        forked = (cudaEventCreateWithFlags(&ev0, cudaEventDisableTiming) == cudaSuccess) &&
                 (cudaEventCreateWithFlags(&ev2, cudaEventDisableTiming) == cudaSuccess);
    }

    prep_all<<<NB_T + NB_PACK, 256>>>(C1, D12, A, B2, B1, C2, D22, D21, D11, x, u,
                                      WbT, WXY, D11T, act);

    // fork immediately after prep: P = [x|u] @ WXY[:, :1536] in two K=768 passes
    if (forked) {
        cudaEventRecord(ev0, 0);
        cudaStreamWaitEvent(s2, ev0, 0);
        ren_gemm<EPI_ST><<<dim3(12, 64), 128, SMEM_BYTES, s2>>>(
            act, LDACT, WXY, 2560, 24, P, 1536, nullptr, 0, nullptr);
        ren_gemm<EPI_ACC><<<dim3(12, 64), 128, SMEM_BYTES, s2>>>(
            act + 768, LDACT, WXY + 768, 2560, 24, P, 1536, P, 1536, nullptr);
        cudaEventRecord(ev2, s2);
    }

    // chain: b = [x|u]@WbT, w0 = tanh(b) -> wA
    ren_gemm<EPI_B><<<dim3(8, 64), 128, SMEM_BYTES>>>(act, LDACT, WbT, 1536, 48,
                                                      b, 1024, nullptr, 0, act + COL_WA);
    if (!forked) {
        ren_gemm<EPI_ST><<<dim3(12, 64), 128, SMEM_BYTES>>>(
            act, LDACT, WXY, 2560, 24, P, 1536, nullptr, 0, nullptr);
        ren_gemm<EPI_ACC><<<dim3(12, 64), 128, SMEM_BYTES>>>(
            act + 768, LDACT, WXY + 768, 2560, 24, P, 1536, P, 1536, nullptr);
    }

    // fixed-point chain: w <- tanh(b + w@D11)
    int cin = COL_WA, cout = COL_WB;
    for (int it = 0; it < N_LOOP; ++it) {
        ren_gemm<EPI_TANH><<<dim3(8, 64), 128, SMEM_BYTES>>>(act + cin, LDACT, D11T, 1024, 32,
                                                             act + cout, LDACT, b, 1024, nullptr);
        int t = cin; cin = cout; cout = t;
    }

    // join, then finals: out = P + w @ WXY[:, 1536:2560]
    if (forked) cudaStreamWaitEvent(0, ev2, 0);
    ren_gemm<EPI_XYP><<<dim3(12, 64), 128, SMEM_BYTES>>>(act + COL_WB, LDACT, WXY + 1536, 2560, 32,
                                                         out, 1024, P, 1536,
                                                         out + (size_t)M_B * 1024);
}

// round 15
// speedup vs baseline: 1.0793x; 1.0793x over previous
#include <cuda_runtime.h>
#include <cuda_fp16.h>
#include <cstdint>

#define M_B    8192
#define LDACT  3584          // halfs per act row: [x | u | wB | wA]
#define COL_WB 1536
#define COL_WA 2560
#define N_LOOP 3             // odd: w0->wA, ends in wB (finals read cols 0..2560)

#define BM 128
#define BN 128
#define BK 32
#define LDSH 40
#define A_HALFS (BM * LDSH)
#define STAGE_HALFS (2 * A_HALFS)
#define STAGE_BYTES (STAGE_HALFS * 2)
#define STAGES 5
#define PREFETCH 4
#define SMEM_BYTES (STAGES * STAGE_BYTES)   // 102400

__device__ __half g_act [(size_t)M_B * LDACT];
__device__ float  g_b   [(size_t)M_B * 1024];
__device__ __half g_WbT [1024 * 1536];
__device__ __half g_WXY [1536 * 2560];
__device__ __half g_D11T[1024 * 1024];

__device__ __forceinline__ uint32_t s2u(const void* p) {
    uint32_t a;
    asm("{ .reg .u64 t; cvta.to.shared.u64 t, %1; cvt.u32.u64 %0, t; }" : "=r"(a) : "l"(p));
    return a;
}
__device__ __forceinline__ void cpa16(uint32_t dst, const void* src) {
    asm volatile("cp.async.cg.shared.global [%0], [%1], 16;" :: "r"(dst), "l"(src) : "memory");
}
__device__ __forceinline__ float fast_tanh(float x) {
    float t = __expf(2.0f * x);
    return 1.0f - __fdividef(2.0f, t + 1.0f);
}
__device__ __forceinline__ void ldm4(uint32_t* r, uint32_t addr) {
    asm volatile("ldmatrix.sync.aligned.m8n8.x4.shared.b16 {%0,%1,%2,%3}, [%4];"
                 : "=r"(r[0]), "=r"(r[1]), "=r"(r[2]), "=r"(r[3]) : "r"(addr));
}
__device__ __forceinline__ void mma_f16(float* d, const uint32_t* a, uint32_t b0, uint32_t b1) {
    asm volatile(
        "mma.sync.aligned.m16n8k16.row.col.f32.f16.f16.f32 "
        "{%0,%1,%2,%3},{%4,%5,%6,%7},{%8,%9},{%0,%1,%2,%3};"
        : "+f"(d[0]), "+f"(d[1]), "+f"(d[2]), "+f"(d[3])
        : "r"(a[0]), "r"(a[1]), "r"(a[2]), "r"(a[3]), "r"(b0), "r"(b1));
}

enum { EPI_TANH = 1, EPI_B = 2, EPI_XY = 3 };

template <int EPI>
__global__ __launch_bounds__(128, 2)
void ren_gemm(const __half* __restrict__ Ap, int lda,
              const __half* __restrict__ Bp, int ldb, int nchunk,
              void* __restrict__ OutV, int ldo,
              const float* __restrict__ Badd, void* __restrict__ Out2V)
{
    extern __shared__ __half sm[];
    const uint32_t smu = s2u(sm);
    const int tid  = threadIdx.x;
    const int lane = tid & 31, wid = tid >> 5;
    const int m0 = blockIdx.y * BM, n0 = blockIdx.x * BN;

    const __half* gA[4]; const __half* gB[4];
    uint32_t oA[4], oB[4];
    #pragma unroll
    for (int i = 0; i < 4; ++i) {
        int c = tid + i * 128;
        int r = c >> 2, ks = c & 3;
        gA[i] = Ap + (size_t)(m0 + r) * lda + ks * 8;
        gB[i] = Bp + (size_t)(n0 + r) * ldb + ks * 8;
        oA[i] = (uint32_t)(r * LDSH + ks * 8) * 2u;
        oB[i] = (uint32_t)(A_HALFS + r * LDSH + ks * 8) * 2u;
    }

    const int l4 = lane >> 2, lq = lane & 3;
    const int mw = (wid >> 1) * 64, nw = (wid & 1) * 64;

    const uint32_t aRow = (uint32_t)(mw + (lane & 7) + (lane & 8)) * LDSH + ((lane & 16) >> 1);
    const uint32_t bRow = (uint32_t)(nw + (lane & 7) + ((lane & 16) >> 1)) * LDSH + (lane & 8);

    float acc[4][8][4];
    #pragma unroll
    for (int i = 0; i < 4; ++i)
        #pragma unroll
        for (int j = 0; j < 8; ++j)
            #pragma unroll
            for (int q = 0; q < 4; ++q) acc[i][j][q] = 0.0f;

    #pragma unroll
    for (int s = 0; s < PREFETCH; ++s) {
        uint32_t sb = smu + s * STAGE_BYTES;
        #pragma unroll
        for (int i = 0; i < 4; ++i) { cpa16(sb + oA[i], gA[i]); gA[i] += BK; }
        #pragma unroll
        for (int i = 0; i < 4; ++i) { cpa16(sb + oB[i], gB[i]); gB[i] += BK; }
        asm volatile("cp.async.commit_group;" ::: "memory");
    }

    int stage = 0;
    for (int c = 0; c < nchunk; ++c) {
        asm volatile("cp.async.wait_group %0;" :: "n"(PREFETCH - 1) : "memory");
        __syncthreads();

        const uint32_t sA = smu + stage * STAGE_BYTES;
        const uint32_t sB = sA + A_HALFS * 2;
        #pragma unroll
        for (int kk = 0; kk < 2; ++kk) {
            uint32_t a[4][4], bf[4][4];
            #pragma unroll
            for (int mt = 0; mt < 4; ++mt)
                ldm4(a[mt], sA + (aRow + mt * 16 * LDSH + kk * 16) * 2);
            #pragma unroll
            for (int nb = 0; nb < 4; ++nb)
                ldm4(bf[nb], sB + (bRow + nb * 16 * LDSH + kk * 16) * 2);
            #pragma unroll
            for (int mt = 0; mt < 4; ++mt)
                #pragma unroll
                for (int nt = 0; nt < 8; ++nt)
                    mma_f16(acc[mt][nt], a[mt],
                            bf[nt >> 1][(nt & 1) * 2], bf[nt >> 1][(nt & 1) * 2 + 1]);
        }

        if (c + PREFETCH < nchunk) {
            int s2 = stage + PREFETCH; if (s2 >= STAGES) s2 -= STAGES;
            uint32_t sb = smu + s2 * STAGE_BYTES;
            #pragma unroll
            for (int i = 0; i < 4; ++i) { cpa16(sb + oA[i], gA[i]); gA[i] += BK; }
            #pragma unroll
            for (int i = 0; i < 4; ++i) { cpa16(sb + oB[i], gB[i]); gB[i] += BK; }
        }
        asm volatile("cp.async.commit_group;" ::: "memory");
        if (++stage == STAGES) stage = 0;
    }

    float* dstF = (float*)OutV; int ldd = ldo, c0 = 0;
    if (EPI == EPI_XY && n0 >= 1024) { dstF = (float*)Out2V; ldd = 512; c0 = 1024; }

    #pragma unroll
    for (int mt = 0; mt < 4; ++mt) {
        #pragma unroll
        for (int half = 0; half < 2; ++half) {
            const int r = m0 + mw + mt * 16 + l4 + half * 8;
            #pragma unroll
            for (int nt = 0; nt < 8; ++nt) {
                const int col = n0 + nw + nt * 8 + lq * 2;
                float v0 = acc[mt][nt][half * 2 + 0];
                float v1 = acc[mt][nt][half * 2 + 1];
                if (EPI == EPI_TANH) {
                    float2 bv = *(const float2*)(Badd + (size_t)r * 1024 + col);
                    __half2 h = __floats2half2_rn(fast_tanh(v0 + bv.x), fast_tanh(v1 + bv.y));
                    *(__half2*)((__half*)OutV + (size_t)r * ldo + col) = h;
                } else if (EPI == EPI_B) {
                    *(float2*)((float*)OutV + (size_t)r * ldo + col) = make_float2(v0, v1);
                    __half2 h = __floats2half2_rn(fast_tanh(v0), fast_tanh(v1));
                    *(__half2*)((__half*)Out2V + (size_t)r * LDACT + col) = h;
                } else {
                    *(float2*)(dstF + (size_t)r * ldd + (col - c0)) = make_float2(v0, v1);
                }
            }
        }
    }
}

// ---- merged prep: 4 weight transposes + activation pack in ONE launch ----
__device__ __forceinline__ void tile_transpose(
    float (*t)[33],
    const float* S0, int K0, const float* S1, int K1, const float* S2, int K2,
    int N, __half* OutT, int ldt, int xb, int yb)
{
    const int k0 = yb * 32, n0 = xb * 32;
    const int tx = threadIdx.x & 31, ty = threadIdx.x >> 5;
    #pragma unroll
    for (int j = 0; j < 4; ++j) {
        int k = k0 + ty + j * 8;
        const float* S; int kk;
        if (k < K0)           { S = S0; kk = k; }
        else if (k < K0 + K1) { S = S1; kk = k - K0; }
        else                  { S = S2; kk = k - K0 - K1; }
        t[ty + j * 8][tx] = S[(size_t)kk * N + n0 + tx];
    }
    __syncthreads();
    #pragma unroll
    for (int j = 0; j < 4; ++j) {
        int n = n0 + ty + j * 8;
        OutT[(size_t)n * ldt + k0 + tx] = __float2half_rn(t[tx][ty + j * 8]);
    }
}

#define NB_WBT  1536
#define NB_WXY1 2560
#define NB_WXY2 1280
#define NB_D11  1024
#define NB_T    (NB_WBT + NB_WXY1 + NB_WXY2 + NB_D11)
#define NB_PACK 12288   // M_B*384 float4 segs / 256 threads

__global__ __launch_bounds__(256)
void prep_all(const float* __restrict__ C1,  const float* __restrict__ D12,
              const float* __restrict__ A,   const float* __restrict__ B2,
              const float* __restrict__ B1,  const float* __restrict__ C2,
              const float* __restrict__ D22, const float* __restrict__ D21,
              const float* __restrict__ D11, const float* __restrict__ x,
              const float* __restrict__ u,
              __half* __restrict__ WbT, __half* __restrict__ WXY,
              __half* __restrict__ D11T, __half* __restrict__ act)
{
    __shared__ float t[32][33];
    int bid = blockIdx.x;
    if (bid < NB_T) {
        if (bid < NB_WBT) {
            tile_transpose(t, C1, 1024, D12, 512, nullptr, 0, 1024,
                           WbT, 1536, bid & 31, bid >> 5);
        } else if (bid < NB_WBT + NB_WXY1) {
            int q = bid - NB_WBT;
            tile_transpose(t, A, 1024, B2, 512, B1, 1024, 1024,
                           WXY, 2560, q & 31, q >> 5);
        } else if (bid < NB_WBT + NB_WXY1 + NB_WXY2) {
            int q = bid - NB_WBT - NB_WXY1;
            tile_transpose(t, C2, 1024, D22, 512, D21, 1024, 512,
                           WXY + (size_t)1024 * 2560, 2560, q & 15, q >> 4);
        } else {
            int q = bid - (NB_WBT + NB_WXY1 + NB_WXY2);
            tile_transpose(t, D11, 1024, nullptr, 0, nullptr, 0, 1024,
                           D11T, 1024, q & 31, q >> 5);
        }
    } else {
        // pack: one float4 (4 fp32) -> one uint2 (4 fp16) per thread
        int idx = (bid - NB_T) * 256 + threadIdx.x;   // over M_B*384 float4 segs
        int row = idx / 384, c4 = idx % 384;
        float4 v = (c4 < 256) ? ((const float4*)x)[(size_t)row * 256 + c4]
                              : ((const float4*)u)[(size_t)row * 128 + (c4 - 256)];
        __half2 h0 = __floats2half2_rn(v.x, v.y);
        __half2 h1 = __floats2half2_rn(v.z, v.w);
        uint2 pk = make_uint2(*(uint32_t*)&h0, *(uint32_t*)&h1);
        ((uint2*)act)[(size_t)row * (LDACT / 4) + c4] = pk;
    }
}

extern "C" void kernel_launch(void* const* d_in, const int* in_sizes, int n_in,
                              void* d_out, int out_size)
{
    (void)in_sizes; (void)n_in; (void)out_size;
    const float* x   = (const float*)d_in[0];
    const float* u   = (const float*)d_in[1];
    const float* A   = (const float*)d_in[2];
    const float* B1  = (const float*)d_in[3];
    const float* B2  = (const float*)d_in[4];
    const float* C1  = (const float*)d_in[5];
    const float* D11 = (const float*)d_in[6];
    const float* D12 = (const float*)d_in[7];
    const float* C2  = (const float*)d_in[8];
    const float* D21 = (const float*)d_in[9];
    const float* D22 = (const float*)d_in[10];
    float* out = (float*)d_out;

    __half *act, *WbT, *WXY, *D11T; float* b;
    cudaGetSymbolAddress((void**)&act,  g_act);
    cudaGetSymbolAddress((void**)&b,    g_b);
    cudaGetSymbolAddress((void**)&WbT,  g_WbT);
    cudaGetSymbolAddress((void**)&WXY,  g_WXY);
    cudaGetSymbolAddress((void**)&D11T, g_D11T);

    cudaFuncSetAttribute((const void*)ren_gemm<EPI_TANH>, cudaFuncAttributeMaxDynamicSharedMemorySize, SMEM_BYTES);
    cudaFuncSetAttribute((const void*)ren_gemm<EPI_B>,    cudaFuncAttributeMaxDynamicSharedMemorySize, SMEM_BYTES);
    cudaFuncSetAttribute((const void*)ren_gemm<EPI_XY>,   cudaFuncAttributeMaxDynamicSharedMemorySize, SMEM_BYTES);

    prep_all<<<NB_T + NB_PACK, 256>>>(C1, D12, A, B2, B1, C2, D22, D21, D11, x, u,
                                      WbT, WXY, D11T, act);

    // b = [x|u] @ [C1;D12]^T (fp32) ; w0 = tanh(b) -> wA slot (odd N_LOOP ends in wB)
    ren_gemm<EPI_B><<<dim3(8, 64), 128, SMEM_BYTES>>>(act, LDACT, WbT, 1536, 48,
                                                      b, 1024, nullptr, act + COL_WA);
    // fixed-point: w <- tanh(b + w@D11)
    int cin = COL_WA, cout = COL_WB;
    for (int it = 0; it < N_LOOP; ++it) {
        ren_gemm<EPI_TANH><<<dim3(8, 64), 128, SMEM_BYTES>>>(act + cin, LDACT, D11T, 1024, 32,
                                                             act + cout, LDACT, b, nullptr);
        int t = cin; cin = cout; cout = t;
    }
    // merged finals: [x|u|w] @ [A;B2;B1 | C2;D22;D21]^T -> x_next (N<1024), y (N>=1024)
    ren_gemm<EPI_XY><<<dim3(12, 64), 128, SMEM_BYTES>>>(act, LDACT, WXY, 2560, 80,
                                                        out, 1024, nullptr,
                                                        out + (size_t)M_B * 1024);
}

// round 16
// speedup vs baseline: 1.0927x; 1.0125x over previous
#include <cuda_runtime.h>
#include <cuda_fp16.h>
#include <cstdint>

#define M_B    8192
#define LDACT  3584          // halfs per act row: [x | u | wB | wA]
#define COL_WB 1536
#define COL_WA 2560
#define N_LOOP 3             // odd: w0->wA, ends in wB (finals read cols 0..2560)

#define BM 128
#define BN 128
#define BK 32
#define LDSH 40
#define A_HALFS (BM * LDSH)
#define STAGE_HALFS (2 * A_HALFS)
#define STAGE_BYTES (STAGE_HALFS * 2)
#define STAGES 5
#define PREFETCH 4
#define SMEM_BYTES (STAGES * STAGE_BYTES)   // 102400

__device__ __half g_act [(size_t)M_B * LDACT];
__device__ float  g_b   [(size_t)M_B * 1024];
__device__ __half g_WbT [1024 * 1536];
__device__ __half g_WXY [1536 * 2560];
__device__ __half g_D11T[1024 * 1024];

__device__ __forceinline__ uint32_t s2u(const void* p) {
    uint32_t a;
    asm("{ .reg .u64 t; cvta.to.shared.u64 t, %1; cvt.u32.u64 %0, t; }" : "=r"(a) : "l"(p));
    return a;
}
__device__ __forceinline__ void cpa16(uint32_t dst, const void* src) {
    asm volatile("cp.async.cg.shared.global [%0], [%1], 16;" :: "r"(dst), "l"(src) : "memory");
}
__device__ __forceinline__ float fast_tanh(float x) {
    float t = __expf(2.0f * x);
    return 1.0f - __fdividef(2.0f, t + 1.0f);
}
__device__ __forceinline__ void ldm4(uint32_t* r, uint32_t addr) {
    asm volatile("ldmatrix.sync.aligned.m8n8.x4.shared.b16 {%0,%1,%2,%3}, [%4];"
                 : "=r"(r[0]), "=r"(r[1]), "=r"(r[2]), "=r"(r[3]) : "r"(addr));
}
__device__ __forceinline__ void mma_f16(float* d, const uint32_t* a, uint32_t b0, uint32_t b1) {
    asm volatile(
        "mma.sync.aligned.m16n8k16.row.col.f32.f16.f16.f32 "
        "{%0,%1,%2,%3},{%4,%5,%6,%7},{%8,%9},{%0,%1,%2,%3};"
        : "+f"(d[0]), "+f"(d[1]), "+f"(d[2]), "+f"(d[3])
        : "r"(a[0]), "r"(a[1]), "r"(a[2]), "r"(a[3]), "r"(b0), "r"(b1));
}
__device__ __forceinline__ void mma_h16(uint32_t* d, const uint32_t* a, uint32_t b0, uint32_t b1) {
    asm volatile(
        "mma.sync.aligned.m16n8k16.row.col.f16.f16.f16.f16 "
        "{%0,%1},{%2,%3,%4,%5},{%6,%7},{%0,%1};"
        : "+r"(d[0]), "+r"(d[1])
        : "r"(a[0]), "r"(a[1]), "r"(a[2]), "r"(a[3]), "r"(b0), "r"(b1));
}

enum { EPI_TANH = 1, EPI_B = 2, EPI_XY = 3 };

template <int EPI>
__global__ __launch_bounds__(128, 2)
void ren_gemm(const __half* __restrict__ Ap, int lda,
              const __half* __restrict__ Bp, int ldb, int nchunk,
              void* __restrict__ OutV, int ldo,
              const float* __restrict__ Badd, void* __restrict__ Out2V)
{
    extern __shared__ __half sm[];
    const uint32_t smu = s2u(sm);
    const int tid  = threadIdx.x;
    const int lane = tid & 31, wid = tid >> 5;
    const int m0 = blockIdx.y * BM, n0 = blockIdx.x * BN;

    const __half* gA[4]; const __half* gB[4];
    uint32_t oA[4], oB[4];
    #pragma unroll
    for (int i = 0; i < 4; ++i) {
        int c = tid + i * 128;
        int r = c >> 2, ks = c & 3;
        gA[i] = Ap + (size_t)(m0 + r) * lda + ks * 8;
        gB[i] = Bp + (size_t)(n0 + r) * ldb + ks * 8;
        oA[i] = (uint32_t)(r * LDSH + ks * 8) * 2u;
        oB[i] = (uint32_t)(A_HALFS + r * LDSH + ks * 8) * 2u;
    }

    const int l4 = lane >> 2, lq = lane & 3;
    const int mw = (wid >> 1) * 64, nw = (wid & 1) * 64;

    const uint32_t aRow = (uint32_t)(mw + (lane & 7) + (lane & 8)) * LDSH + ((lane & 16) >> 1);
    const uint32_t bRow = (uint32_t)(nw + (lane & 7) + ((lane & 16) >> 1)) * LDSH + (lane & 8);

    float acc[4][8][4];
    #pragma unroll
    for (int i = 0; i < 4; ++i)
        #pragma unroll
        for (int j = 0; j < 8; ++j)
            #pragma unroll
            for (int q = 0; q < 4; ++q) acc[i][j][q] = 0.0f;

    #pragma unroll
    for (int s = 0; s < PREFETCH; ++s) {
        uint32_t sb = smu + s * STAGE_BYTES;
        #pragma unroll
        for (int i = 0; i < 4; ++i) { cpa16(sb + oA[i], gA[i]); gA[i] += BK; }
        #pragma unroll
        for (int i = 0; i < 4; ++i) { cpa16(sb + oB[i], gB[i]); gB[i] += BK; }
        asm volatile("cp.async.commit_group;" ::: "memory");
    }

    int stage = 0;
    for (int c = 0; c < nchunk; ++c) {
        asm volatile("cp.async.wait_group %0;" :: "n"(PREFETCH - 1) : "memory");
        __syncthreads();

        const uint32_t sA = smu + stage * STAGE_BYTES;
        const uint32_t sB = sA + A_HALFS * 2;
        #pragma unroll
        for (int kk = 0; kk < 2; ++kk) {
            uint32_t a[4][4], bf[4][4];
            #pragma unroll
            for (int mt = 0; mt < 4; ++mt)
                ldm4(a[mt], sA + (aRow + mt * 16 * LDSH + kk * 16) * 2);
            #pragma unroll
            for (int nb = 0; nb < 4; ++nb)
                ldm4(bf[nb], sB + (bRow + nb * 16 * LDSH + kk * 16) * 2);
            #pragma unroll
            for (int mt = 0; mt < 4; ++mt)
                #pragma unroll
                for (int nt = 0; nt < 8; ++nt)
                    mma_f16(acc[mt][nt], a[mt],
                            bf[nt >> 1][(nt & 1) * 2], bf[nt >> 1][(nt & 1) * 2 + 1]);
        }

        if (c + PREFETCH < nchunk) {
            int s2 = stage + PREFETCH; if (s2 >= STAGES) s2 -= STAGES;
            uint32_t sb = smu + s2 * STAGE_BYTES;
            #pragma unroll
            for (int i = 0; i < 4; ++i) { cpa16(sb + oA[i], gA[i]); gA[i] += BK; }
            #pragma unroll
            for (int i = 0; i < 4; ++i) { cpa16(sb + oB[i], gB[i]); gB[i] += BK; }
        }
        asm volatile("cp.async.commit_group;" ::: "memory");
        if (++stage == STAGES) stage = 0;
    }

    float* dstF = (float*)OutV; int ldd = ldo, c0 = 0;
    if (EPI == EPI_XY && n0 >= 1024) { dstF = (float*)Out2V; ldd = 512; c0 = 1024; }

    #pragma unroll
    for (int mt = 0; mt < 4; ++mt) {
        #pragma unroll
        for (int half = 0; half < 2; ++half) {
            const int r = m0 + mw + mt * 16 + l4 + half * 8;
            #pragma unroll
            for (int nt = 0; nt < 8; ++nt) {
                const int col = n0 + nw + nt * 8 + lq * 2;
                float v0 = acc[mt][nt][half * 2 + 0];
                float v1 = acc[mt][nt][half * 2 + 1];
                if (EPI == EPI_TANH) {
                    float2 bv = *(const float2*)(Badd + (size_t)r * 1024 + col);
                    __half2 h = __floats2half2_rn(fast_tanh(v0 + bv.x), fast_tanh(v1 + bv.y));
                    *(__half2*)((__half*)OutV + (size_t)r * ldo + col) = h;
                } else if (EPI == EPI_B) {
                    *(float2*)((float*)OutV + (size_t)r * ldo + col) = make_float2(v0, v1);
                    __half2 h = __floats2half2_rn(fast_tanh(v0), fast_tanh(v1));
                    *(__half2*)((__half*)Out2V + (size_t)r * LDACT + col) = h;
                } else {
                    *(float2*)(dstF + (size_t)r * ldd + (col - c0)) = make_float2(v0, v1);
                }
            }
        }
    }
}

// fp16-accumulate loop-iteration kernel (tanh epilogue only).
// Same loader/mainloop; accumulators are half2 pairs.
__global__ __launch_bounds__(128, 2)
void ren_gemm_h16(const __half* __restrict__ Ap, int lda,
                  const __half* __restrict__ Bp, int ldb, int nchunk,
                  __half* __restrict__ Out, int ldo,
                  const float* __restrict__ Badd)
{
    extern __shared__ __half sm[];
    const uint32_t smu = s2u(sm);
    const int tid  = threadIdx.x;
    const int lane = tid & 31, wid = tid >> 5;
    const int m0 = blockIdx.y * BM, n0 = blockIdx.x * BN;

    const __half* gA[4]; const __half* gB[4];
    uint32_t oA[4], oB[4];
    #pragma unroll
    for (int i = 0; i < 4; ++i) {
        int c = tid + i * 128;
        int r = c >> 2, ks = c & 3;
        gA[i] = Ap + (size_t)(m0 + r) * lda + ks * 8;
        gB[i] = Bp + (size_t)(n0 + r) * ldb + ks * 8;
        oA[i] = (uint32_t)(r * LDSH + ks * 8) * 2u;
        oB[i] = (uint32_t)(A_HALFS + r * LDSH + ks * 8) * 2u;
    }

    const int l4 = lane >> 2, lq = lane & 3;
    const int mw = (wid >> 1) * 64, nw = (wid & 1) * 64;

    const uint32_t aRow = (uint32_t)(mw + (lane & 7) + (lane & 8)) * LDSH + ((lane & 16) >> 1);
    const uint32_t bRow = (uint32_t)(nw + (lane & 7) + ((lane & 16) >> 1)) * LDSH + (lane & 8);

    uint32_t acc[4][8][2];
    #pragma unroll
    for (int i = 0; i < 4; ++i)
        #pragma unroll
        for (int j = 0; j < 8; ++j) { acc[i][j][0] = 0u; acc[i][j][1] = 0u; }

    #pragma unroll
    for (int s = 0; s < PREFETCH; ++s) {
        uint32_t sb = smu + s * STAGE_BYTES;
        #pragma unroll
        for (int i = 0; i < 4; ++i) { cpa16(sb + oA[i], gA[i]); gA[i] += BK; }
        #pragma unroll
        for (int i = 0; i < 4; ++i) { cpa16(sb + oB[i], gB[i]); gB[i] += BK; }
        asm volatile("cp.async.commit_group;" ::: "memory");
    }

    int stage = 0;
    for (int c = 0; c < nchunk; ++c) {
        asm volatile("cp.async.wait_group %0;" :: "n"(PREFETCH - 1) : "memory");
        __syncthreads();

        const uint32_t sA = smu + stage * STAGE_BYTES;
        const uint32_t sB = sA + A_HALFS * 2;
        #pragma unroll
        for (int kk = 0; kk < 2; ++kk) {
            uint32_t a[4][4], bf[4][4];
            #pragma unroll
            for (int mt = 0; mt < 4; ++mt)
                ldm4(a[mt], sA + (aRow + mt * 16 * LDSH + kk * 16) * 2);
            #pragma unroll
            for (int nb = 0; nb < 4; ++nb)
                ldm4(bf[nb], sB + (bRow + nb * 16 * LDSH + kk * 16) * 2);
            #pragma unroll
            for (int mt = 0; mt < 4; ++mt)
                #pragma unroll
                for (int nt = 0; nt < 8; ++nt)
                    mma_h16(acc[mt][nt], a[mt],
                            bf[nt >> 1][(nt & 1) * 2], bf[nt >> 1][(nt & 1) * 2 + 1]);
        }

        if (c + PREFETCH < nchunk) {
            int s2 = stage + PREFETCH; if (s2 >= STAGES) s2 -= STAGES;
            uint32_t sb = smu + s2 * STAGE_BYTES;
            #pragma unroll
            for (int i = 0; i < 4; ++i) { cpa16(sb + oA[i], gA[i]); gA[i] += BK; }
            #pragma unroll
            for (int i = 0; i < 4; ++i) { cpa16(sb + oB[i], gB[i]); gB[i] += BK; }
        }
        asm volatile("cp.async.commit_group;" ::: "memory");
        if (++stage == STAGES) stage = 0;
    }

    #pragma unroll
    for (int mt = 0; mt < 4; ++mt) {
        #pragma unroll
        for (int half = 0; half < 2; ++half) {
            const int r = m0 + mw + mt * 16 + l4 + half * 8;
            #pragma unroll
            for (int nt = 0; nt < 8; ++nt) {
                const int col = n0 + nw + nt * 8 + lq * 2;
                uint32_t hv = acc[mt][nt][half];
                __half2 hh = *(__half2*)&hv;
                float v0 = __low2float(hh), v1 = __high2float(hh);
                float2 bv = *(const float2*)(Badd + (size_t)r * 1024 + col);
                __half2 h = __floats2half2_rn(fast_tanh(v0 + bv.x), fast_tanh(v1 + bv.y));
                *(__half2*)(Out + (size_t)r * ldo + col) = h;
            }
        }
    }
}

// ---- merged prep: 4 weight transposes + activation pack in ONE launch ----
__device__ __forceinline__ void tile_transpose(
    float (*t)[33],
    const float* S0, int K0, const float* S1, int K1, const float* S2, int K2,
    int N, __half* OutT, int ldt, int xb, int yb)
{
    const int k0 = yb * 32, n0 = xb * 32;
    const int tx = threadIdx.x & 31, ty = threadIdx.x >> 5;
    #pragma unroll
    for (int j = 0; j < 4; ++j) {
        int k = k0 + ty + j * 8;
        const float* S; int kk;
        if (k < K0)           { S = S0; kk = k; }
        else if (k < K0 + K1) { S = S1; kk = k - K0; }
        else                  { S = S2; kk = k - K0 - K1; }
        t[ty + j * 8][tx] = S[(size_t)kk * N + n0 + tx];
    }
    __syncthreads();
    #pragma unroll
    for (int j = 0; j < 4; ++j) {
        int n = n0 + ty + j * 8;
        OutT[(size_t)n * ldt + k0 + tx] = __float2half_rn(t[tx][ty + j * 8]);
    }
}

#define NB_WBT  1536
#define NB_WXY1 2560
#define NB_WXY2 1280
#define NB_D11  1024
#define NB_T    (NB_WBT + NB_WXY1 + NB_WXY2 + NB_D11)
#define NB_PACK 12288   // M_B*384 float4 segs / 256 threads

__global__ __launch_bounds__(256)
void prep_all(const float* __restrict__ C1,  const float* __restrict__ D12,
              const float* __restrict__ A,   const float* __restrict__ B2,
              const float* __restrict__ B1,  const float* __restrict__ C2,
              const float* __restrict__ D22, const float* __restrict__ D21,
              const float* __restrict__ D11, const float* __restrict__ x,
              const float* __restrict__ u,
              __half* __restrict__ WbT, __half* __restrict__ WXY,
              __half* __restrict__ D11T, __half* __restrict__ act)
{
    __shared__ float t[32][33];
    int bid = blockIdx.x;
    if (bid < NB_T) {
        if (bid < NB_WBT) {
            tile_transpose(t, C1, 1024, D12, 512, nullptr, 0, 1024,
                           WbT, 1536, bid & 31, bid >> 5);
        } else if (bid < NB_WBT + NB_WXY1) {
            int q = bid - NB_WBT;
            tile_transpose(t, A, 1024, B2, 512, B1, 1024, 1024,
                           WXY, 2560, q & 31, q >> 5);
        } else if (bid < NB_WBT + NB_WXY1 + NB_WXY2) {
            int q = bid - NB_WBT - NB_WXY1;
            tile_transpose(t, C2, 1024, D22, 512, D21, 1024, 512,
                           WXY + (size_t)1024 * 2560, 2560, q & 15, q >> 4);
        } else {
            int q = bid - (NB_WBT + NB_WXY1 + NB_WXY2);
            tile_transpose(t, D11, 1024, nullptr, 0, nullptr, 0, 1024,
                           D11T, 1024, q & 31, q >> 5);
        }
    } else {
        int idx = (bid - NB_T) * 256 + threadIdx.x;   // over M_B*384 float4 segs
        int row = idx / 384, c4 = idx % 384;
        float4 v = (c4 < 256) ? ((const float4*)x)[(size_t)row * 256 + c4]
                              : ((const float4*)u)[(size_t)row * 128 + (c4 - 256)];
        __half2 h0 = __floats2half2_rn(v.x, v.y);
        __half2 h1 = __floats2half2_rn(v.z, v.w);
        uint2 pk = make_uint2(*(uint32_t*)&h0, *(uint32_t*)&h1);
        ((uint2*)act)[(size_t)row * (LDACT / 4) + c4] = pk;
    }
}

extern "C" void kernel_launch(void* const* d_in, const int* in_sizes, int n_in,
                              void* d_out, int out_size)
{
    (void)in_sizes; (void)n_in; (void)out_size;
    const float* x   = (const float*)d_in[0];
    const float* u   = (const float*)d_in[1];
    const float* A   = (const float*)d_in[2];
    const float* B1  = (const float*)d_in[3];
    const float* B2  = (const float*)d_in[4];
    const float* C1  = (const float*)d_in[5];
    const float* D11 = (const float*)d_in[6];
    const float* D12 = (const float*)d_in[7];
    const float* C2  = (const float*)d_in[8];
    const float* D21 = (const float*)d_in[9];
    const float* D22 = (const float*)d_in[10];
    float* out = (float*)d_out;

    __half *act, *WbT, *WXY, *D11T; float* b;
    cudaGetSymbolAddress((void**)&act,  g_act);
    cudaGetSymbolAddress((void**)&b,    g_b);
    cudaGetSymbolAddress((void**)&WbT,  g_WbT);
    cudaGetSymbolAddress((void**)&WXY,  g_WXY);
    cudaGetSymbolAddress((void**)&D11T, g_D11T);

    cudaFuncSetAttribute((const void*)ren_gemm<EPI_TANH>, cudaFuncAttributeMaxDynamicSharedMemorySize, SMEM_BYTES);
    cudaFuncSetAttribute((const void*)ren_gemm<EPI_B>,    cudaFuncAttributeMaxDynamicSharedMemorySize, SMEM_BYTES);
    cudaFuncSetAttribute((const void*)ren_gemm<EPI_XY>,   cudaFuncAttributeMaxDynamicSharedMemorySize, SMEM_BYTES);
    cudaFuncSetAttribute((const void*)ren_gemm_h16,       cudaFuncAttributeMaxDynamicSharedMemorySize, SMEM_BYTES);

    prep_all<<<NB_T + NB_PACK, 256>>>(C1, D12, A, B2, B1, C2, D22, D21, D11, x, u,
                                      WbT, WXY, D11T, act);

    // b = [x|u] @ [C1;D12]^T (fp32) ; w0 = tanh(b) -> wA slot (odd N_LOOP ends in wB)
    ren_gemm<EPI_B><<<dim3(8, 64), 128, SMEM_BYTES>>>(act, LDACT, WbT, 1536, 48,
                                                      b, 1024, nullptr, act + COL_WA);
    // fixed-point: w <- tanh(b + w@D11)
    // iterations 0..N_LOOP-2: fp16 accumulate (noise contracted by later iterations)
    // last iteration: fp32 accumulate (feeds finals)
    int cin = COL_WA, cout = COL_WB;
    for (int it = 0; it < N_LOOP; ++it) {
        if (it < N_LOOP - 1) {
            ren_gemm_h16<<<dim3(8, 64), 128, SMEM_BYTES>>>(act + cin, LDACT, D11T, 1024, 32,
                                                           act + cout, LDACT, b);
        } else {
            ren_gemm<EPI_TANH><<<dim3(8, 64), 128, SMEM_BYTES>>>(act + cin, LDACT, D11T, 1024, 32,
                                                                 act + cout, LDACT, b, nullptr);
        }
        int t = cin; cin = cout; cout = t;
    }
    // merged finals: [x|u|w] @ [A;B2;B1 | C2;D22;D21]^T -> x_next (N<1024), y (N>=1024)
    ren_gemm<EPI_XY><<<dim3(12, 64), 128, SMEM_BYTES>>>(act, LDACT, WXY, 2560, 80,
                                                        out, 1024, nullptr,
                                                        out + (size_t)M_B * 1024);
}